// round 10
// baseline (speedup 1.0000x reference)
#include <cuda_runtime.h>

#define K 19
#define L 2048
#define B 512
#define START_ID 17
#define PAD_ID 18
#define NEG -1000.0f
#define NW 4            // rows (warps) per block
#define NSEG 16         // backtrack segments per row
#define CPL 10          // boundary chains per lane: ceil(16*19/32)
#define FULL 0xffffffffu
#define ROWBYTES (L / 8 * 160)  // packed bp: [L/8 groups][20 lanes][8 bytes]

__device__ int g_elt4;

__global__ void detect_kernel(const unsigned char* __restrict__ m) {
    __shared__ int found;
    if (threadIdx.x == 0) found = 0;
    __syncthreads();
    int f = 0;
    for (int i = threadIdx.x * 4 + 1; i < 65536; i += blockDim.x * 4)
        f |= m[i];
    if (f) found = 1;
    __syncthreads();
    if (threadIdx.x == 0) g_elt4 = found ? 0 : 1;
}

// bp(t, c): group t/8, 20 lanes x 8 bytes
__device__ __forceinline__ int BPGET(const unsigned char* bp, int t, int c) {
    return bp[((t >> 3) * 160) + (c << 3) + (t & 7)];
}

// ---- A-step: exchange + value max only (the critical path) ----
#define ASTEP(CUR, NXT, EMIT, S, BV) do {                                  \
    float d[20];                                                           \
    *(float4*)&d[0]  = *(const float4*)&dpbuf[wid][CUR][0];                \
    *(float4*)&d[4]  = *(const float4*)&dpbuf[wid][CUR][4];                \
    *(float4*)&d[8]  = *(const float4*)&dpbuf[wid][CUR][8];                \
    *(float4*)&d[12] = *(const float4*)&dpbuf[wid][CUR][12];               \
    *(float4*)&d[16] = *(const float4*)&dpbuf[wid][CUR][16];               \
    S[0]=d[0]+Trow[0];   S[1]=d[1]+Trow[1];   S[2]=d[2]+Trow[2];           \
    S[3]=d[3]+Trow[3];   S[4]=d[4]+Trow[4];   S[5]=d[5]+Trow[5];           \
    S[6]=d[6]+Trow[6];   S[7]=d[7]+Trow[7];   S[8]=d[8]+Trow[8];           \
    S[9]=d[9]+Trow[9];   S[10]=d[10]+Trow[10];S[11]=d[11]+Trow[11];        \
    S[12]=d[12]+Trow[12];S[13]=d[13]+Trow[13];S[14]=d[14]+Trow[14];        \
    S[15]=d[15]+Trow[15];S[16]=d[16]+Trow[16];S[17]=d[17]+Trow[17];        \
    S[18]=d[18]+Trow[18];                                                  \
    float m0=fmaxf(S[0],S[1]),  m1=fmaxf(S[2],S[3]),  m2=fmaxf(S[4],S[5]); \
    float m3=fmaxf(S[6],S[7]),  m4=fmaxf(S[8],S[9]),  m5=fmaxf(S[10],S[11]);\
    float m6=fmaxf(S[12],S[13]),m7=fmaxf(S[14],S[15]),m8=fmaxf(S[16],S[17]);\
    m0=fmaxf(m0,m1); m2=fmaxf(m2,m3); m4=fmaxf(m4,m5); m6=fmaxf(m6,m7);    \
    m8=fmaxf(m8,S[18]);                                                    \
    m0=fmaxf(m0,m2); m4=fmaxf(m4,m6);                                      \
    m0=fmaxf(m0,m4); BV=fmaxf(m0,m8);                                      \
    nd = BV + (EMIT);                                                      \
    dpbuf[wid][NXT][lane] = nd;                                            \
    __syncwarp();                                                          \
} while (0)

// ---- B-step: first-occurrence argmax + byte pack (off critical path) ----
#define BSTEP(S, BV, PH) do {                                              \
    unsigned mb = 0u;                                                      \
    _Pragma("unroll")                                                      \
    for (int k2 = 0; k2 < K; ++k2)                                         \
        mb |= (S[k2] == (BV)) ? (1u << k2) : 0u;                           \
    unsigned argb = (unsigned)(__ffs(mb) - 1);                             \
    if ((PH) == 0)      w0 = argb;                                         \
    else if ((PH) < 4)  w0 |= argb << (8 * (PH));                          \
    else if ((PH) == 4) w1 = argb;                                         \
    else                w1 |= argb << (8 * ((PH) - 4));                    \
    if ((PH) == 7) {                                                       \
        if (lane < K)                                                      \
            *bpq = (unsigned long long)w0 |                                \
                   ((unsigned long long)w1 << 32);                         \
        bpq += 20;                                                         \
    }                                                                      \
} while (0)

__global__ void __launch_bounds__(NW * 32, 1) viterbi_kernel(
    const float* __restrict__ P,          // [B, L, K]
    const float* __restrict__ Tm,         // [K, K]: T[j*K+k], prev k -> cur j
    const unsigned char* __restrict__ mask,
    float* __restrict__ out)              // [B, L] float32
{
    extern __shared__ unsigned char dsm[];            // NW * ROWBYTES
    __shared__ __align__(16) float dpbuf[NW][2][32];  // padded DP double buffer
    __shared__ unsigned char fmap[NW][NSEG][K];
    __shared__ unsigned char eseg[NW][NSEG];

    const int wid  = threadIdx.x >> 5;
    const int lane = threadIdx.x & 31;
    const int b    = blockIdx.x * NW + wid;
    const int j    = (lane < K) ? lane : 0;

    unsigned char* __restrict__ bp = dsm + wid * ROWBYTES;

    // ---- sequence length ----
    int len = 0;
    if (g_elt4) {
        const unsigned int* m = (const unsigned int*)mask + (size_t)b * L;
        for (int i = lane; i < L; i += 32) len += (m[i] != 0u);
    } else {
        const unsigned char* m = mask + (size_t)b * L;
        for (int i = lane; i < L; i += 32) len += (m[i] != 0);
    }
#pragma unroll
    for (int o = 16; o; o >>= 1) len += __shfl_xor_sync(FULL, len, o);

    float Trow[K];
#pragma unroll
    for (int k = 0; k < K; ++k) Trow[k] = Tm[j * K + k];

    const float* Pb = P + (size_t)b * L * K;

    // init DP buffers (slots 19..31 padding)
    dpbuf[wid][0][lane] = (lane == START_ID) ? 0.0f : NEG;
    dpbuf[wid][1][lane] = NEG;
    __syncwarp();

    float nd = (j == START_ID && lane < K) ? 0.0f : NEG;
    unsigned long long* bpq = (unsigned long long*)bp + lane;
    unsigned w0 = 0, w1 = 0;
    float s0[K], s1[K], b0, b1;

    if (len >= 24) {
        const float* ep = Pb + j;
        float e0 = __ldg(ep + 0 * K), e1 = __ldg(ep + 1 * K);
        float e2 = __ldg(ep + 2 * K), e3 = __ldg(ep + 3 * K);
        float e4 = __ldg(ep + 4 * K), e5 = __ldg(ep + 5 * K);
        float e6 = __ldg(ep + 6 * K), e7 = __ldg(ep + 7 * K);
        ep += 8 * K;

        // prologue group: steps 0..7 (no B for step -1)
        ASTEP(0,1,e0,s0,b0); e0 = __ldg(ep + 0 * K);
        ASTEP(1,0,e1,s1,b1); e1 = __ldg(ep + 1 * K); BSTEP(s0,b0,0);
        ASTEP(0,1,e2,s0,b0); e2 = __ldg(ep + 2 * K); BSTEP(s1,b1,1);
        ASTEP(1,0,e3,s1,b1); e3 = __ldg(ep + 3 * K); BSTEP(s0,b0,2);
        ASTEP(0,1,e4,s0,b0); e4 = __ldg(ep + 4 * K); BSTEP(s1,b1,3);
        ASTEP(1,0,e5,s1,b1); e5 = __ldg(ep + 5 * K); BSTEP(s0,b0,4);
        ASTEP(0,1,e6,s0,b0); e6 = __ldg(ep + 6 * K); BSTEP(s1,b1,5);
        ASTEP(1,0,e7,s1,b1); e7 = __ldg(ep + 7 * K); BSTEP(s0,b0,6);
        ep += 8 * K;

        int t = 8;
        // main loop: steps t..t+7, B lags by one (B(t-1) first, phase 7)
        for (; t + 16 <= len; t += 8) {
            ASTEP(0,1,e0,s0,b0); e0 = __ldg(ep + 0 * K); BSTEP(s1,b1,7);
            ASTEP(1,0,e1,s1,b1); e1 = __ldg(ep + 1 * K); BSTEP(s0,b0,0);
            ASTEP(0,1,e2,s0,b0); e2 = __ldg(ep + 2 * K); BSTEP(s1,b1,1);
            ASTEP(1,0,e3,s1,b1); e3 = __ldg(ep + 3 * K); BSTEP(s0,b0,2);
            ASTEP(0,1,e4,s0,b0); e4 = __ldg(ep + 4 * K); BSTEP(s1,b1,3);
            ASTEP(1,0,e5,s1,b1); e5 = __ldg(ep + 5 * K); BSTEP(s0,b0,4);
            ASTEP(0,1,e6,s0,b0); e6 = __ldg(ep + 6 * K); BSTEP(s1,b1,5);
            ASTEP(1,0,e7,s1,b1); e7 = __ldg(ep + 7 * K); BSTEP(s0,b0,6);
            ep += 8 * K;
        }

        // epilogue: pending B(t-1), then r = len-t (8..15) guarded steps
        BSTEP(s1,b1,7);
        const int r = len - t;
        // slots 0..7: emissions already in e0..e7
        if (r > 0) { ASTEP(0,1,e0,s0,b0); BSTEP(s0,b0,0); }
        if (r > 1) { ASTEP(1,0,e1,s1,b1); BSTEP(s1,b1,1); }
        if (r > 2) { ASTEP(0,1,e2,s0,b0); BSTEP(s0,b0,2); }
        if (r > 3) { ASTEP(1,0,e3,s1,b1); BSTEP(s1,b1,3); }
        if (r > 4) { ASTEP(0,1,e4,s0,b0); BSTEP(s0,b0,4); }
        if (r > 5) { ASTEP(1,0,e5,s1,b1); BSTEP(s1,b1,5); }
        if (r > 6) { ASTEP(0,1,e6,s0,b0); BSTEP(s0,b0,6); }
        if (r > 7) { ASTEP(1,0,e7,s1,b1); BSTEP(s1,b1,7); }
        // slots 8..14: direct emission loads
        if (r > 8)  { float ex = __ldg(Pb + j + (t + 8) * K);
                      ASTEP(0,1,ex,s0,b0); BSTEP(s0,b0,0); }
        if (r > 9)  { float ex = __ldg(Pb + j + (t + 9) * K);
                      ASTEP(1,0,ex,s1,b1); BSTEP(s1,b1,1); }
        if (r > 10) { float ex = __ldg(Pb + j + (t + 10) * K);
                      ASTEP(0,1,ex,s0,b0); BSTEP(s0,b0,2); }
        if (r > 11) { float ex = __ldg(Pb + j + (t + 11) * K);
                      ASTEP(1,0,ex,s1,b1); BSTEP(s1,b1,3); }
        if (r > 12) { float ex = __ldg(Pb + j + (t + 12) * K);
                      ASTEP(0,1,ex,s0,b0); BSTEP(s0,b0,4); }
        if (r > 13) { float ex = __ldg(Pb + j + (t + 13) * K);
                      ASTEP(1,0,ex,s1,b1); BSTEP(s1,b1,5); }
        if (r > 14) { float ex = __ldg(Pb + j + (t + 14) * K);
                      ASTEP(0,1,ex,s0,b0); BSTEP(s0,b0,6); }
        // flush partial word (phases 0..6 of the last group)
        if (r > 8 && lane < K)
            *bpq = (unsigned long long)w0 | ((unsigned long long)w1 << 32);
    } else {
        // ---- slow path: len < 24 ----
        float* cb = dpbuf[wid][0];
        float* nb = dpbuf[wid][1];
        for (int s2 = 0; s2 < len; ++s2) {
            const float emit = __ldg(Pb + j + s2 * K);
            float d[20];
            *(float4*)&d[0]  = *(const float4*)&cb[0];
            *(float4*)&d[4]  = *(const float4*)&cb[4];
            *(float4*)&d[8]  = *(const float4*)&cb[8];
            *(float4*)&d[12] = *(const float4*)&cb[12];
            *(float4*)&d[16] = *(const float4*)&cb[16];
#pragma unroll
            for (int k = 0; k < K; ++k) s0[k] = d[k] + Trow[k];
            float best = s0[0];
#pragma unroll
            for (int k = 1; k < K; ++k) best = fmaxf(best, s0[k]);
            unsigned mb = 0u;
#pragma unroll
            for (int k = 0; k < K; ++k) mb |= (s0[k] == best) ? (1u << k) : 0u;
            nd = best + emit;
            nb[lane] = nd;
            __syncwarp();
            float* tmp = cb; cb = nb; nb = tmp;
            if (lane < K)
                bp[((s2 >> 3) * 160) + (lane << 3) + (s2 & 7)] =
                    (unsigned char)(__ffs(mb) - 1);
        }
        __syncwarp();
    }

    // ---- final transition into PAD, first-occurrence argmax ----
    const float fv = (lane < K) ? (nd + Tm[PAD_ID * K + j]) : NEG;
    int last = 0;
    {
        float bestf = __shfl_sync(FULL, fv, 0);
#pragma unroll
        for (int k = 1; k < K; ++k) {
            const float vk = __shfl_sync(FULL, fv, k);
            if (vk > bestf) { bestf = vk; last = k; }
        }
    }

    float* ob = out + (size_t)b * L;
    for (int tt = len + lane; tt < L; tt += 32) ob[tt] = -1.0f;

    // ---- backtrack, warp-local two-pass ----
    const int segw = (len + NSEG - 1) / NSEG;
    const int nseg = (len + segw - 1) / segw;

    int cur[CPL], tq[CPL], t0q[CPL];
#pragma unroll
    for (int q = 0; q < CPL; ++q) {
        const int cid = lane + 32 * q;
        if (cid < nseg * K) {
            const int i = cid / K, e = cid - i * K;
            const int t0 = i * segw;
            const int t1 = min(t0 + segw, len);
            cur[q] = e; tq[q] = t1 - 1; t0q[q] = t0;
        } else { cur[q] = 0; tq[q] = 0; t0q[q] = 0; }
    }
    for (int p = 0; p < segw - 1; ++p) {
#pragma unroll
        for (int q = 0; q < CPL; ++q)
            if (tq[q] > t0q[q]) {
                cur[q] = BPGET(bp, tq[q], cur[q]);
                tq[q]--;
            }
    }
#pragma unroll
    for (int q = 0; q < CPL; ++q) {
        const int cid = lane + 32 * q;
        if (cid < nseg * K) {
            const int i = cid / K, e = cid - i * K;
            fmap[wid][i][e] = (unsigned char)cur[q];
        }
    }
    __syncwarp();

    if (lane == 0) {
        int e = last;
        eseg[wid][nseg - 1] = (unsigned char)e;
        for (int i = nseg - 1; i > 0; --i) {
            const int t0 = i * segw;
            const int pc = fmap[wid][i][e];       // path[t0]
            e = BPGET(bp, t0, pc);                // path[t0-1]
            eseg[wid][i - 1] = (unsigned char)e;
        }
    }
    __syncwarp();

    if (lane < nseg) {
        const int t0 = lane * segw;
        const int t1 = min(t0 + segw, len);
        int c = eseg[wid][lane];
        ob[t1 - 1] = (float)c;
        for (int tt = t1 - 2; tt >= t0; --tt) {
            c = BPGET(bp, tt + 1, c);
            ob[tt] = (float)c;
        }
    }
}

extern "C" void kernel_launch(void* const* d_in, const int* in_sizes, int n_in,
                              void* d_out, int out_size) {
    const float* P = (const float*)d_in[0];
    const float* T = (const float*)d_in[1];
    const unsigned char* mask = (const unsigned char*)d_in[2];
    float* out = (float*)d_out;

    const int smem = NW * ROWBYTES;  // 163840 B
    cudaFuncSetAttribute(viterbi_kernel,
                         cudaFuncAttributeMaxDynamicSharedMemorySize, smem);

    detect_kernel<<<1, 256>>>(mask);
    viterbi_kernel<<<B / NW, NW * 32, smem>>>(P, T, mask, out);
}

// round 11
// speedup vs baseline: 1.0957x; 1.0957x over previous
#include <cuda_runtime.h>

#define K 19
#define L 2048
#define B 512
#define START_ID 17
#define PAD_ID 18
#define NEG -1000.0f
#define NW 4            // rows (warps) per block
#define NSEG 16         // backtrack segments per row
#define CPL 10          // boundary chains per lane: ceil(16*19/32)
#define FULL 0xffffffffu
#define ROWBYTES (L / 8 * 160)  // packed bp: [L/8 groups][20 lanes][8 bytes]

__device__ int g_elt4;

__global__ void detect_kernel(const unsigned char* __restrict__ m) {
    __shared__ int found;
    if (threadIdx.x == 0) found = 0;
    __syncthreads();
    int f = 0;
    for (int i = threadIdx.x * 4 + 1; i < 65536; i += blockDim.x * 4)
        f |= m[i];
    if (f) found = 1;
    __syncthreads();
    if (threadIdx.x == 0) g_elt4 = found ? 0 : 1;
}

// bp(t, c): group t/8, 20 lanes x 8 bytes
__device__ __forceinline__ int BPGET(const unsigned char* bp, int t, int c) {
    return bp[((t >> 3) * 160) + (c << 3) + (t & 7)];
}

__device__ __forceinline__ unsigned smem_u32(const void* p) {
    unsigned a;
    asm("{ .reg .u64 t; cvta.to.shared.u64 t, %1; cvt.u32.u64 %0, t; }"
        : "=r"(a) : "l"(p));
    return a;
}

// ---- A-step: warp-synchronous exchange + value max (NO syncwarp).
// All dpbuf traffic via asm volatile: compiler keeps program order; the LSU
// processes one warp's SMEM ops in order, so the next step's LDS sees this
// step's STS without a barrier (warp stays converged; lane<K is predication).
#define ASTEP(SRC, DST, EMIT, S, BV) do {                                  \
    float dum_;                                                            \
    asm volatile("ld.shared.v4.f32 {%0,%1,%2,%3}, [%4];"                   \
        : "=f"(S[0]), "=f"(S[1]), "=f"(S[2]), "=f"(S[3])                   \
        : "r"(SRC) : "memory");                                            \
    asm volatile("ld.shared.v4.f32 {%0,%1,%2,%3}, [%4];"                   \
        : "=f"(S[4]), "=f"(S[5]), "=f"(S[6]), "=f"(S[7])                   \
        : "r"((SRC) + 16) : "memory");                                     \
    asm volatile("ld.shared.v4.f32 {%0,%1,%2,%3}, [%4];"                   \
        : "=f"(S[8]), "=f"(S[9]), "=f"(S[10]), "=f"(S[11])                 \
        : "r"((SRC) + 32) : "memory");                                     \
    asm volatile("ld.shared.v4.f32 {%0,%1,%2,%3}, [%4];"                   \
        : "=f"(S[12]), "=f"(S[13]), "=f"(S[14]), "=f"(S[15])               \
        : "r"((SRC) + 48) : "memory");                                     \
    asm volatile("ld.shared.v4.f32 {%0,%1,%2,%3}, [%4];"                   \
        : "=f"(S[16]), "=f"(S[17]), "=f"(S[18]), "=f"(dum_)                \
        : "r"((SRC) + 64) : "memory");                                     \
    S[0]+=Trow[0];   S[1]+=Trow[1];   S[2]+=Trow[2];   S[3]+=Trow[3];      \
    S[4]+=Trow[4];   S[5]+=Trow[5];   S[6]+=Trow[6];   S[7]+=Trow[7];      \
    S[8]+=Trow[8];   S[9]+=Trow[9];   S[10]+=Trow[10]; S[11]+=Trow[11];    \
    S[12]+=Trow[12]; S[13]+=Trow[13]; S[14]+=Trow[14]; S[15]+=Trow[15];    \
    S[16]+=Trow[16]; S[17]+=Trow[17]; S[18]+=Trow[18];                     \
    float m0=fmaxf(S[0],S[1]),  m1=fmaxf(S[2],S[3]),  m2=fmaxf(S[4],S[5]); \
    float m3=fmaxf(S[6],S[7]),  m4=fmaxf(S[8],S[9]),  m5=fmaxf(S[10],S[11]);\
    float m6=fmaxf(S[12],S[13]),m7=fmaxf(S[14],S[15]),m8=fmaxf(S[16],S[17]);\
    m0=fmaxf(m0,m1); m2=fmaxf(m2,m3); m4=fmaxf(m4,m5); m6=fmaxf(m6,m7);    \
    m8=fmaxf(m8,S[18]);                                                    \
    m0=fmaxf(m0,m2); m4=fmaxf(m4,m6);                                      \
    m0=fmaxf(m0,m4); BV=fmaxf(m0,m8);                                      \
    nd = BV + (EMIT);                                                      \
    asm volatile("st.shared.f32 [%0], %1;"                                 \
        :: "r"((DST) + laneoff), "f"(nd) : "memory");                      \
} while (0)

// ---- B-step: first-occurrence argmax + byte pack (off critical path) ----
#define BSTEP(S, BV, PH) do {                                              \
    unsigned mb = 0u;                                                      \
    _Pragma("unroll")                                                      \
    for (int k2 = 0; k2 < K; ++k2)                                         \
        mb |= (S[k2] == (BV)) ? (1u << k2) : 0u;                           \
    unsigned argb = (unsigned)(__ffs(mb) - 1);                             \
    if ((PH) == 0)      w0 = argb;                                         \
    else if ((PH) < 4)  w0 |= argb << (8 * (PH));                          \
    else if ((PH) == 4) w1 = argb;                                         \
    else                w1 |= argb << (8 * ((PH) - 4));                    \
    if ((PH) == 7) {                                                       \
        if (lane < K)                                                      \
            *bpq = (unsigned long long)w0 |                                \
                   ((unsigned long long)w1 << 32);                         \
        bpq += 20;                                                         \
    }                                                                      \
} while (0)

__global__ void __launch_bounds__(NW * 32, 1) viterbi_kernel(
    const float* __restrict__ P,          // [B, L, K]
    const float* __restrict__ Tm,         // [K, K]: T[j*K+k], prev k -> cur j
    const unsigned char* __restrict__ mask,
    float* __restrict__ out)              // [B, L] float32
{
    extern __shared__ unsigned char dsm[];            // NW * ROWBYTES
    __shared__ __align__(16) float dpbuf[NW][2][32];  // padded DP double buffer
    __shared__ unsigned char fmap[NW][NSEG][K];
    __shared__ unsigned char eseg[NW][NSEG];

    const int wid  = threadIdx.x >> 5;
    const int lane = threadIdx.x & 31;
    const int b    = blockIdx.x * NW + wid;
    const int j    = (lane < K) ? lane : 0;
    const unsigned laneoff = (unsigned)lane << 2;

    unsigned char* __restrict__ bp = dsm + wid * ROWBYTES;

    // ---- sequence length ----
    int len = 0;
    if (g_elt4) {
        const unsigned int* m = (const unsigned int*)mask + (size_t)b * L;
        for (int i = lane; i < L; i += 32) len += (m[i] != 0u);
    } else {
        const unsigned char* m = mask + (size_t)b * L;
        for (int i = lane; i < L; i += 32) len += (m[i] != 0);
    }
#pragma unroll
    for (int o = 16; o; o >>= 1) len += __shfl_xor_sync(FULL, len, o);

    float Trow[K];
#pragma unroll
    for (int k = 0; k < K; ++k) Trow[k] = Tm[j * K + k];

    const float* Pb = P + (size_t)b * L * K;

    // init DP buffers (slots 19..31 padding)
    dpbuf[wid][0][lane] = (lane == START_ID) ? 0.0f : NEG;
    dpbuf[wid][1][lane] = NEG;
    __syncwarp();

    const unsigned dpA = smem_u32(&dpbuf[wid][0][0]);
    const unsigned dpB = dpA + 128;

    float nd = (j == START_ID && lane < K) ? 0.0f : NEG;
    unsigned long long* bpq = (unsigned long long*)bp + lane;
    unsigned w0 = 0, w1 = 0;
    float s0[K], s1[K], b0, b1;

    if (len >= 24) {
        const float* ep = Pb + j;
        float e0 = __ldg(ep + 0 * K), e1 = __ldg(ep + 1 * K);
        float e2 = __ldg(ep + 2 * K), e3 = __ldg(ep + 3 * K);
        float e4 = __ldg(ep + 4 * K), e5 = __ldg(ep + 5 * K);
        float e6 = __ldg(ep + 6 * K), e7 = __ldg(ep + 7 * K);
        ep += 8 * K;

        // prologue group: steps 0..7
        ASTEP(dpA,dpB,e0,s0,b0); e0 = __ldg(ep + 0 * K);
        ASTEP(dpB,dpA,e1,s1,b1); e1 = __ldg(ep + 1 * K); BSTEP(s0,b0,0);
        ASTEP(dpA,dpB,e2,s0,b0); e2 = __ldg(ep + 2 * K); BSTEP(s1,b1,1);
        ASTEP(dpB,dpA,e3,s1,b1); e3 = __ldg(ep + 3 * K); BSTEP(s0,b0,2);
        ASTEP(dpA,dpB,e4,s0,b0); e4 = __ldg(ep + 4 * K); BSTEP(s1,b1,3);
        ASTEP(dpB,dpA,e5,s1,b1); e5 = __ldg(ep + 5 * K); BSTEP(s0,b0,4);
        ASTEP(dpA,dpB,e6,s0,b0); e6 = __ldg(ep + 6 * K); BSTEP(s1,b1,5);
        ASTEP(dpB,dpA,e7,s1,b1); e7 = __ldg(ep + 7 * K); BSTEP(s0,b0,6);
        ep += 8 * K;

        int t = 8;
        // main loop: steps t..t+7, B lags by one
        for (; t + 16 <= len; t += 8) {
            ASTEP(dpA,dpB,e0,s0,b0); e0 = __ldg(ep + 0 * K); BSTEP(s1,b1,7);
            ASTEP(dpB,dpA,e1,s1,b1); e1 = __ldg(ep + 1 * K); BSTEP(s0,b0,0);
            ASTEP(dpA,dpB,e2,s0,b0); e2 = __ldg(ep + 2 * K); BSTEP(s1,b1,1);
            ASTEP(dpB,dpA,e3,s1,b1); e3 = __ldg(ep + 3 * K); BSTEP(s0,b0,2);
            ASTEP(dpA,dpB,e4,s0,b0); e4 = __ldg(ep + 4 * K); BSTEP(s1,b1,3);
            ASTEP(dpB,dpA,e5,s1,b1); e5 = __ldg(ep + 5 * K); BSTEP(s0,b0,4);
            ASTEP(dpA,dpB,e6,s0,b0); e6 = __ldg(ep + 6 * K); BSTEP(s1,b1,5);
            ASTEP(dpB,dpA,e7,s1,b1); e7 = __ldg(ep + 7 * K); BSTEP(s0,b0,6);
            ep += 8 * K;
        }

        // epilogue: pending B(t-1), then r = len-t (8..15) guarded steps
        BSTEP(s1,b1,7);
        const int r = len - t;
        if (r > 0) { ASTEP(dpA,dpB,e0,s0,b0); BSTEP(s0,b0,0); }
        if (r > 1) { ASTEP(dpB,dpA,e1,s1,b1); BSTEP(s1,b1,1); }
        if (r > 2) { ASTEP(dpA,dpB,e2,s0,b0); BSTEP(s0,b0,2); }
        if (r > 3) { ASTEP(dpB,dpA,e3,s1,b1); BSTEP(s1,b1,3); }
        if (r > 4) { ASTEP(dpA,dpB,e4,s0,b0); BSTEP(s0,b0,4); }
        if (r > 5) { ASTEP(dpB,dpA,e5,s1,b1); BSTEP(s1,b1,5); }
        if (r > 6) { ASTEP(dpA,dpB,e6,s0,b0); BSTEP(s0,b0,6); }
        if (r > 7) { ASTEP(dpB,dpA,e7,s1,b1); BSTEP(s1,b1,7); }
        if (r > 8)  { float ex = __ldg(Pb + j + (t + 8) * K);
                      ASTEP(dpA,dpB,ex,s0,b0); BSTEP(s0,b0,0); }
        if (r > 9)  { float ex = __ldg(Pb + j + (t + 9) * K);
                      ASTEP(dpB,dpA,ex,s1,b1); BSTEP(s1,b1,1); }
        if (r > 10) { float ex = __ldg(Pb + j + (t + 10) * K);
                      ASTEP(dpA,dpB,ex,s0,b0); BSTEP(s0,b0,2); }
        if (r > 11) { float ex = __ldg(Pb + j + (t + 11) * K);
                      ASTEP(dpB,dpA,ex,s1,b1); BSTEP(s1,b1,3); }
        if (r > 12) { float ex = __ldg(Pb + j + (t + 12) * K);
                      ASTEP(dpA,dpB,ex,s0,b0); BSTEP(s0,b0,4); }
        if (r > 13) { float ex = __ldg(Pb + j + (t + 13) * K);
                      ASTEP(dpB,dpA,ex,s1,b1); BSTEP(s1,b1,5); }
        if (r > 14) { float ex = __ldg(Pb + j + (t + 14) * K);
                      ASTEP(dpA,dpB,ex,s0,b0); BSTEP(s0,b0,6); }
        if (r > 8 && lane < K)
            *bpq = (unsigned long long)w0 | ((unsigned long long)w1 << 32);
    } else {
        // ---- slow path: len < 24 (barrier version, rare) ----
        float* cb = dpbuf[wid][0];
        float* nb = dpbuf[wid][1];
        for (int s2 = 0; s2 < len; ++s2) {
            const float emit = __ldg(Pb + j + s2 * K);
            float d[20];
            *(float4*)&d[0]  = *(const float4*)&cb[0];
            *(float4*)&d[4]  = *(const float4*)&cb[4];
            *(float4*)&d[8]  = *(const float4*)&cb[8];
            *(float4*)&d[12] = *(const float4*)&cb[12];
            *(float4*)&d[16] = *(const float4*)&cb[16];
#pragma unroll
            for (int k = 0; k < K; ++k) s0[k] = d[k] + Trow[k];
            float best = s0[0];
#pragma unroll
            for (int k = 1; k < K; ++k) best = fmaxf(best, s0[k]);
            unsigned mb = 0u;
#pragma unroll
            for (int k = 0; k < K; ++k) mb |= (s0[k] == best) ? (1u << k) : 0u;
            nd = best + emit;
            nb[lane] = nd;
            __syncwarp();
            float* tmp = cb; cb = nb; nb = tmp;
            if (lane < K)
                bp[((s2 >> 3) * 160) + (lane << 3) + (s2 & 7)] =
                    (unsigned char)(__ffs(mb) - 1);
        }
    }
    __syncwarp();

    // ---- final transition into PAD, first-occurrence argmax ----
    const float fv = (lane < K) ? (nd + Tm[PAD_ID * K + j]) : NEG;
    int last = 0;
    {
        float bestf = __shfl_sync(FULL, fv, 0);
#pragma unroll
        for (int k = 1; k < K; ++k) {
            const float vk = __shfl_sync(FULL, fv, k);
            if (vk > bestf) { bestf = vk; last = k; }
        }
    }

    float* ob = out + (size_t)b * L;
    for (int tt = len + lane; tt < L; tt += 32) ob[tt] = -1.0f;

    // ---- backtrack, warp-local two-pass ----
    const int segw = (len + NSEG - 1) / NSEG;
    const int nseg = (len + segw - 1) / segw;

    int cur[CPL], tq[CPL], t0q[CPL];
#pragma unroll
    for (int q = 0; q < CPL; ++q) {
        const int cid = lane + 32 * q;
        if (cid < nseg * K) {
            const int i = cid / K, e = cid - i * K;
            const int t0 = i * segw;
            const int t1 = min(t0 + segw, len);
            cur[q] = e; tq[q] = t1 - 1; t0q[q] = t0;
        } else { cur[q] = 0; tq[q] = 0; t0q[q] = 0; }
    }
    for (int p = 0; p < segw - 1; ++p) {
#pragma unroll
        for (int q = 0; q < CPL; ++q)
            if (tq[q] > t0q[q]) {
                cur[q] = BPGET(bp, tq[q], cur[q]);
                tq[q]--;
            }
    }
#pragma unroll
    for (int q = 0; q < CPL; ++q) {
        const int cid = lane + 32 * q;
        if (cid < nseg * K) {
            const int i = cid / K, e = cid - i * K;
            fmap[wid][i][e] = (unsigned char)cur[q];
        }
    }
    __syncwarp();

    if (lane == 0) {
        int e = last;
        eseg[wid][nseg - 1] = (unsigned char)e;
        for (int i = nseg - 1; i > 0; --i) {
            const int t0 = i * segw;
            const int pc = fmap[wid][i][e];       // path[t0]
            e = BPGET(bp, t0, pc);                // path[t0-1]
            eseg[wid][i - 1] = (unsigned char)e;
        }
    }
    __syncwarp();

    if (lane < nseg) {
        const int t0 = lane * segw;
        const int t1 = min(t0 + segw, len);
        int c = eseg[wid][lane];
        ob[t1 - 1] = (float)c;
        for (int tt = t1 - 2; tt >= t0; --tt) {
            c = BPGET(bp, tt + 1, c);
            ob[tt] = (float)c;
        }
    }
}

extern "C" void kernel_launch(void* const* d_in, const int* in_sizes, int n_in,
                              void* d_out, int out_size) {
    const float* P = (const float*)d_in[0];
    const float* T = (const float*)d_in[1];
    const unsigned char* mask = (const unsigned char*)d_in[2];
    float* out = (float*)d_out;

    const int smem = NW * ROWBYTES;  // 163840 B
    cudaFuncSetAttribute(viterbi_kernel,
                         cudaFuncAttributeMaxDynamicSharedMemorySize, smem);

    detect_kernel<<<1, 256>>>(mask);
    viterbi_kernel<<<B / NW, NW * 32, smem>>>(P, T, mask, out);
}